// round 5
// baseline (speedup 1.0000x reference)
#include <cuda_runtime.h>
#include <cstdint>

// Problem constants
#define P       4096
#define MDIM    64          // hidden feature dim
#define M2      32          // f32x2 count per row (64 floats)
#define BI      256         // rows per block (row tile)
#define NJ      16          // j-splits
#define JR      (P / NJ)    // 256 j per block
#define JT      128         // j tile staged in shared
#define NTILE   (JR / JT)   // 2
#define THREADS 256

// Scratch (allocation-free per harness rules): partial sums + partial counts.
// g_partial: [NJ][P][64] floats stored as u64 pairs = 16 MB
__device__ unsigned long long g_partial[(size_t)NJ * P * M2];
__device__ int g_kpart[NJ * P];
__device__ int g_any;

__device__ __forceinline__ void ffma2(unsigned long long &d,
                                      unsigned long long a,
                                      unsigned long long b) {
    // d = a*b + d  (packed 2x fp32)
    asm("fma.rn.f32x2 %0, %1, %2, %0;" : "+l"(d) : "l"(a), "l"(b));
}

// ---------------------------------------------------------------------------
// Kernel A: per (row-tile, j-split) partial masked sums + neighbor counts.
// Grid: (P/BI = 16, NJ = 16). Block: 256 threads.
// Thread map: mg = tid&3 owns 16 floats (8 f32x2), i_g = tid>>2 owns rows
// {i_g, i_g+64, i_g+128, i_g+192} of the tile (4 rows x 8 f32x2 accumulators).
// NOTE: nei_index arrives as int32 (JAX x64-disabled downcasts jnp.int64).
// ---------------------------------------------------------------------------
__global__ void __launch_bounds__(THREADS)
partial_kernel(const float* __restrict__ hidden,
               const int* __restrict__ nei) {
    __shared__ ulonglong2 s_hu[JT][16];      // hidden tile: 128 x 64 floats = 32 KB
    __shared__ unsigned   s_bits[BI][4];     // mask bits: 256 rows x 128 j = 4 KB

    const int tid  = threadIdx.x;
    const int lane = tid & 31;
    const int wid  = tid >> 5;
    const int mg   = tid & 3;
    const int i_g  = tid >> 2;

    const int i0 = blockIdx.x * BI;
    const int j0 = blockIdx.y * JR;

    unsigned long long acc[4][8];
#pragma unroll
    for (int r = 0; r < 4; r++)
#pragma unroll
        for (int c = 0; c < 8; c++) acc[r][c] = 0ULL;

    int cnt = 0;   // neighbor count for row (i0 + tid) over this j-range

    const float4* hid4 = (const float4*)hidden;

    for (int t = 0; t < NTILE; t++) {
        const int jbase = j0 + t * JT;
        if (t) __syncthreads();   // previous tile fully consumed

        // --- stage hidden tile: JT rows x 16 float4 ---
#pragma unroll
        for (int k = 0; k < (JT * 16) / THREADS; k++) {
            int idx = tid + k * THREADS;
            int jj = idx >> 4, q = idx & 15;
            ((float4*)s_hu)[jj * 16 + q] = hid4[(size_t)(jbase + jj) * 16 + q];
        }

        // --- build mask bits via ballot: 256 rows x 4 words of 32 j ---
        for (int c = wid; c < BI * 4; c += (THREADS / 32)) {
            int row = c >> 2, wq = c & 3;
            int j = jbase + wq * 32 + lane;
            int v = (nei[(size_t)(i0 + row) * P + j] > 0) ? 1 : 0;
            unsigned b = __ballot_sync(0xffffffffu, v);
            if (lane == 0) s_bits[row][wq] = b;
        }
        __syncthreads();

        // --- per-row neighbor count (thread tid owns row tid) ---
#pragma unroll
        for (int wq = 0; wq < 4; wq++) cnt += __popc(s_bits[tid][wq]);

        // --- masked accumulation, register-tiled 4 rows x 8 f32x2 ---
#pragma unroll 1
        for (int wq = 0; wq < 4; wq++) {
            unsigned wb0 = s_bits[i_g       ][wq];
            unsigned wb1 = s_bits[i_g +  64 ][wq];
            unsigned wb2 = s_bits[i_g + 128 ][wq];
            unsigned wb3 = s_bits[i_g + 192 ][wq];
#pragma unroll 8
            for (int b = 0; b < 32; b++) {
                const int jj = wq * 32 + b;
                ulonglong2 hv0 = s_hu[jj][mg * 4 + 0];
                ulonglong2 hv1 = s_hu[jj][mg * 4 + 1];
                ulonglong2 hv2 = s_hu[jj][mg * 4 + 2];
                ulonglong2 hv3 = s_hu[jj][mg * 4 + 3];
                unsigned wb[4] = {wb0, wb1, wb2, wb3};
#pragma unroll
                for (int r = 0; r < 4; r++) {
                    unsigned long long fmm =
                        ((wb[r] >> b) & 1u) ? 0x3F8000003F800000ULL : 0ULL;
                    ffma2(acc[r][0], hv0.x, fmm);
                    ffma2(acc[r][1], hv0.y, fmm);
                    ffma2(acc[r][2], hv1.x, fmm);
                    ffma2(acc[r][3], hv1.y, fmm);
                    ffma2(acc[r][4], hv2.x, fmm);
                    ffma2(acc[r][5], hv2.y, fmm);
                    ffma2(acc[r][6], hv3.x, fmm);
                    ffma2(acc[r][7], hv3.y, fmm);
                }
            }
        }
    }

    // --- write partials (exclusive regions, no atomics) ---
    unsigned long long* gp = g_partial + (size_t)blockIdx.y * P * M2;
#pragma unroll
    for (int r = 0; r < 4; r++) {
        size_t base = (size_t)(i0 + i_g + 64 * r) * M2 + mg * 8;
#pragma unroll
        for (int c = 0; c < 8; c++) gp[base + c] = acc[r][c];
    }
    g_kpart[blockIdx.y * P + i0 + tid] = cnt;
}

// ---------------------------------------------------------------------------
// Kernel A2: global "any neighbor" flag (recomputed fresh every launch — graph
// replay safe).
// ---------------------------------------------------------------------------
__global__ void any_kernel() {
    __shared__ int sr[256];
    int t = threadIdx.x;
    int a = 0;
    for (int idx = t; idx < NJ * P; idx += 256) a |= g_kpart[idx];
    sr[t] = a;
    __syncthreads();
    for (int s = 128; s > 0; s >>= 1) {
        if (t < s) sr[t] |= sr[t + s];
        __syncthreads();
    }
    if (t == 0) g_any = sr[0];
}

// ---------------------------------------------------------------------------
// Kernel B: reduce NJ partials, apply row softmax scalar c_i, any_nei fallback.
// Grid: P*64/256 = 1024 blocks of 256.
// ---------------------------------------------------------------------------
__global__ void finalize_kernel(const float* __restrict__ hidden,
                                float* __restrict__ out) {
    int g = blockIdx.x * blockDim.x + threadIdx.x;   // 0 .. P*MDIM-1
    int i = g >> 6;
    const float* gp = (const float*)g_partial;
    float s = 0.0f;
    int k = 0;
#pragma unroll
    for (int nj = 0; nj < NJ; nj++) {
        s += gp[(size_t)nj * P * MDIM + g];
        k += g_kpart[nj * P + i];
    }
    float kf = (float)k;
    // softmax row max = 1 (any neighbor): neighbor weight = 1 / (k + (P-k)*e^{-1.000001})
    float denom = kf + (4096.0f - kf) * expf(-1.000001f);
    float c = 1.0f / denom;
    out[g] = (g_any > 0) ? (c * s) : hidden[g];
}

// ---------------------------------------------------------------------------
extern "C" void kernel_launch(void* const* d_in, const int* in_sizes, int n_in,
                              void* d_out, int out_size) {
    const float* hidden = nullptr;
    const int* nei = nullptr;
    // identify inputs by element count (robust to ordering):
    // hidden: 4096*64 = 262144 ; nei: 4096*4096 = 16777216 ; corr: 33554432 (unused)
    for (int i = 0; i < n_in; i++) {
        if (in_sizes[i] == P * MDIM)      hidden = (const float*)d_in[i];
        else if (in_sizes[i] == P * P)    nei    = (const int*)d_in[i];
    }
    float* out = (float*)d_out;

    dim3 gridA(P / BI, NJ);
    partial_kernel<<<gridA, THREADS>>>(hidden, nei);
    any_kernel<<<1, 256>>>();
    finalize_kernel<<<(P * MDIM) / 256, 256>>>(hidden, out);
    (void)out_size;
}

// round 9
// speedup vs baseline: 1.7243x; 1.7243x over previous
#include <cuda_runtime.h>
#include <cuda_bf16.h>
#include <cstdint>

#define P       4096
#define MDIM    64
#define NB      72           // padded N: 64 features + count col + pad (ldmatrix stride 144B)
#define NJ      16           // K-splits
#define KC      (P / NJ)     // 256 K per CTA
#define MTILE   128          // rows per CTA (8 warps x 16)
#define THREADS 256

#define BROW    144          // SMEM/global B row stride bytes (72 bf16)
#define BPLANE  (4096 * NB)  // elements per hi/lo plane
#define SM_PLANE (KC * BROW) // 36864 B per plane in SMEM
#define SM_TOTAL (2 * SM_PLANE)

// ---- scratch (allocation-free) ----
__device__ float g_partial[(size_t)NJ * P * NB];           // 18.9 MB
__device__ int   g_any;
__device__ __nv_bfloat16 g_B[2][4096][NB];                 // hi/lo: hidden^T padded

// ---- helpers ----
__device__ __forceinline__ uint32_t smem_u32(const void* p) {
    uint32_t a;
    asm("{ .reg .u64 t; cvta.to.shared.u64 t, %1; cvt.u32.u64 %0, t; }" : "=r"(a) : "l"(p));
    return a;
}
__device__ __forceinline__ uint32_t pack01(int x, int y) {
    return (x > 0 ? 0x3F80u : 0u) | (y > 0 ? 0x3F800000u : 0u);
}
__device__ __forceinline__ void ldsm_x2_t(uint32_t& r0, uint32_t& r1, uint32_t addr) {
    asm volatile("ldmatrix.sync.aligned.m8n8.x2.trans.shared.b16 {%0,%1}, [%2];"
                 : "=r"(r0), "=r"(r1) : "r"(addr));
}
__device__ __forceinline__ void mma16816(float* d, const uint32_t* a, uint32_t b0, uint32_t b1) {
    asm volatile("mma.sync.aligned.m16n8k16.row.col.f32.bf16.bf16.f32 "
                 "{%0,%1,%2,%3}, {%4,%5,%6,%7}, {%8,%9}, {%0,%1,%2,%3};"
                 : "+f"(d[0]), "+f"(d[1]), "+f"(d[2]), "+f"(d[3])
                 : "r"(a[0]), "r"(a[1]), "r"(a[2]), "r"(a[3]), "r"(b0), "r"(b1));
}

// ---------------------------------------------------------------------------
// prep: hidden [4096][64] f32 -> g_B hi/lo [4096][72] bf16 (exact split).
// col 64 = ones (hi) / zeros (lo) -> GEMM emits neighbor counts. cols 65-71 = 0.
// ---------------------------------------------------------------------------
__global__ void prep_kernel(const float* __restrict__ hidden) {
    int k = blockIdx.x * blockDim.y + threadIdx.y;   // 0..4095
    int n = threadIdx.x;                             // 0..71
    float v = (n < MDIM) ? hidden[(size_t)k * MDIM + n] : (n == MDIM ? 1.0f : 0.0f);
    __nv_bfloat16 h = __float2bfloat16(v);
    __nv_bfloat16 l = __float2bfloat16(v - __bfloat162float(h));
    g_B[0][k][n] = h;
    g_B[1][k][n] = l;
}

// ---------------------------------------------------------------------------
// mma_kernel: grid (32 M-tiles, 16 K-splits), 256 threads, 8 warps x 16 rows.
// A fragments built in registers from nei (int32 -> bf16 {0,1}); B via
// ldmatrix.x2.trans from SMEM; mma.sync m16n8k16 bf16, fp32 accum.
// ---------------------------------------------------------------------------
__global__ void __launch_bounds__(THREADS, 3)
mma_kernel(const int* __restrict__ nei) {
    extern __shared__ char smem[];
    const uint32_t sb = smem_u32(smem);

    const int tid  = threadIdx.x;
    const int wid  = tid >> 5;
    const int lane = tid & 31;
    const int g    = lane >> 2;      // fragment row group 0..7
    const int tq   = lane & 3;       // fragment k/col group 0..3

    const int i0 = blockIdx.x * MTILE;
    const int ks = blockIdx.y;
    const int k0 = ks * KC;

    // --- stage B hi/lo slice [KC][72] into SMEM (rows contiguous in global) ---
    {
        const uint4* s0 = (const uint4*)&g_B[0][k0][0];
        const uint4* s1 = (const uint4*)&g_B[1][k0][0];
        uint4* d0 = (uint4*)smem;
        uint4* d1 = (uint4*)(smem + SM_PLANE);
#pragma unroll
        for (int it = 0; it < SM_PLANE / 16 / THREADS; it++) {
            int idx = tid + it * THREADS;
            d0[idx] = s0[idx];
            d1[idx] = s1[idx];
        }
    }
    __syncthreads();

    const int row = i0 + wid * 16 + g;          // this lane's fragment rows: row, row+8

    float d[9][4];
#pragma unroll
    for (int nf = 0; nf < 9; nf++)
#pragma unroll
        for (int c = 0; c < 4; c++) d[nf][c] = 0.0f;

#pragma unroll 2
    for (int t = 0; t < KC / 16; t++) {
        // --- A fragment from nei: rows {row,row+8}, k cols {tq*2,+1, tq*2+8,+9} ---
        const int* pa = nei + (size_t)row * P + k0 + t * 16 + tq * 2;
        int2 v00 = *(const int2*)(pa);
        int2 v01 = *(const int2*)(pa + 8);
        int2 v10 = *(const int2*)(pa + (size_t)8 * P);
        int2 v11 = *(const int2*)(pa + (size_t)8 * P + 8);
        uint32_t a[4];
        a[0] = pack01(v00.x, v00.y);
        a[1] = pack01(v10.x, v10.y);
        a[2] = pack01(v01.x, v01.y);
        a[3] = pack01(v11.x, v11.y);

        // --- B fragments: ldmatrix.x2.trans, rows t*16+(lane&15), col block nf*8 ---
        const uint32_t lrow = sb + (t * 16 + (lane & 15)) * BROW;

        uint32_t bh[9][2];
#pragma unroll
        for (int nf = 0; nf < 9; nf++) ldsm_x2_t(bh[nf][0], bh[nf][1], lrow + nf * 16);
#pragma unroll
        for (int nf = 0; nf < 9; nf++) mma16816(d[nf], a, bh[nf][0], bh[nf][1]);

        uint32_t bl[8][2];
#pragma unroll
        for (int nf = 0; nf < 8; nf++) ldsm_x2_t(bl[nf][0], bl[nf][1], lrow + SM_PLANE + nf * 16);
#pragma unroll
        for (int nf = 0; nf < 8; nf++) mma16816(d[nf], a, bl[nf][0], bl[nf][1]);
    }

    // --- write partials [ks][row][72] (cols 0-63 sums, 64 count, 65-71 zero) ---
    float* gp0 = g_partial + ((size_t)ks * P + row) * NB + tq * 2;
    float* gp1 = gp0 + (size_t)8 * NB;
#pragma unroll
    for (int nf = 0; nf < 9; nf++) {
        *(float2*)(gp0 + nf * 8) = make_float2(d[nf][0], d[nf][1]);
        *(float2*)(gp1 + nf * 8) = make_float2(d[nf][2], d[nf][3]);
    }
}

// ---------------------------------------------------------------------------
__global__ void any_kernel() {
    __shared__ int sr[256];
    int t = threadIdx.x;
    int a = 0;
    for (int idx = t; idx < NJ * P; idx += 256)
        a |= (g_partial[(size_t)idx * NB + MDIM] > 0.5f) ? 1 : 0;
    sr[t] = a;
    __syncthreads();
    for (int s = 128; s > 0; s >>= 1) {
        if (t < s) sr[t] |= sr[t + s];
        __syncthreads();
    }
    if (t == 0) g_any = sr[0];
}

__global__ void finalize_kernel(const float* __restrict__ hidden,
                                float* __restrict__ out) {
    int gidx = blockIdx.x * blockDim.x + threadIdx.x;   // 0 .. P*64-1
    int i = gidx >> 6, c = gidx & 63;
    float s = 0.0f, kf = 0.0f;
#pragma unroll
    for (int nj = 0; nj < NJ; nj++) {
        const float* rp = g_partial + ((size_t)nj * P + i) * NB;
        s  += rp[c];
        kf += rp[MDIM];
    }
    float denom = kf + (4096.0f - kf) * expf(-1.000001f);
    float cs = 1.0f / denom;
    out[gidx] = (g_any > 0) ? (cs * s) : hidden[gidx];
}

// ---------------------------------------------------------------------------
extern "C" void kernel_launch(void* const* d_in, const int* in_sizes, int n_in,
                              void* d_out, int out_size) {
    const float* hidden = nullptr;
    const int* nei = nullptr;
    for (int i = 0; i < n_in; i++) {
        if (in_sizes[i] == P * MDIM)   hidden = (const float*)d_in[i];
        else if (in_sizes[i] == P * P) nei    = (const int*)d_in[i];
    }
    float* out = (float*)d_out;

    static bool attr_set = false;
    if (!attr_set) {
        cudaFuncSetAttribute(mma_kernel, cudaFuncAttributeMaxDynamicSharedMemorySize, SM_TOTAL);
        attr_set = true;
    }

    prep_kernel<<<4096 / 8, dim3(NB, 8)>>>(hidden);
    mma_kernel<<<dim3(P / MTILE, NJ), THREADS, SM_TOTAL>>>(nei);
    any_kernel<<<1, 256>>>();
    finalize_kernel<<<(P * MDIM) / 256, 256>>>(hidden, out);
    (void)out_size;
}

// round 12
// speedup vs baseline: 3.4595x; 2.0063x over previous
#include <cuda_runtime.h>
#include <cuda_bf16.h>
#include <cstdint>

#define P       4096
#define MDIM    64
#define NB      72           // padded N: 64 features + count col + pad (ldmatrix stride 144B)
#define NJ      16           // K-splits
#define KC      (P / NJ)     // 256 K per CTA
#define MTILE   128          // rows per CTA (8 warps x 16)
#define THREADS 256

#define BROW    144          // SMEM/global B row stride bytes (72 bf16)
#define SM_PLANE (KC * BROW) // 36864 B per plane in SMEM
#define SM_TOTAL (2 * SM_PLANE)

// ---- scratch (allocation-free) ----
__device__ float g_acc[P][NB];                 // accumulated sums + counts (1.2 MB)
__device__ int   g_any;
__device__ __nv_bfloat16 g_B[2][4096][NB];     // hi/lo: hidden^T padded

// ---- helpers ----
__device__ __forceinline__ uint32_t smem_u32(const void* p) {
    uint32_t a;
    asm("{ .reg .u64 t; cvta.to.shared.u64 t, %1; cvt.u32.u64 %0, t; }" : "=r"(a) : "l"(p));
    return a;
}
__device__ __forceinline__ uint32_t pack01(int x, int y) {
    return (x > 0 ? 0x3F80u : 0u) | (y > 0 ? 0x3F800000u : 0u);
}
__device__ __forceinline__ void ldsm_x2_t(uint32_t& r0, uint32_t& r1, uint32_t addr) {
    asm volatile("ldmatrix.sync.aligned.m8n8.x2.trans.shared.b16 {%0,%1}, [%2];"
                 : "=r"(r0), "=r"(r1) : "r"(addr));
}
__device__ __forceinline__ void mma16816(float* d, const uint32_t* a, uint32_t b0, uint32_t b1) {
    asm volatile("mma.sync.aligned.m16n8k16.row.col.f32.bf16.bf16.f32 "
                 "{%0,%1,%2,%3}, {%4,%5,%6,%7}, {%8,%9}, {%0,%1,%2,%3};"
                 : "+f"(d[0]), "+f"(d[1]), "+f"(d[2]), "+f"(d[3])
                 : "r"(a[0]), "r"(a[1]), "r"(a[2]), "r"(a[3]), "r"(b0), "r"(b1));
}

// ---------------------------------------------------------------------------
// prep: hidden [4096][64] f32 -> g_B hi/lo [4096][72] bf16 (exact split).
// col 64 = ones (hi) / zeros (lo) -> GEMM emits neighbor counts.
// Also zeroes g_acc and g_any every launch (graph-replay safe: stream order
// guarantees this completes before mma_kernel's atomics).
// ---------------------------------------------------------------------------
__global__ void prep_kernel(const float* __restrict__ hidden) {
    int k = blockIdx.x * blockDim.y + threadIdx.y;   // 0..4095
    int n = threadIdx.x;                             // 0..71
    float v = (n < MDIM) ? hidden[(size_t)k * MDIM + n] : (n == MDIM ? 1.0f : 0.0f);
    __nv_bfloat16 h = __float2bfloat16(v);
    __nv_bfloat16 l = __float2bfloat16(v - __bfloat162float(h));
    g_B[0][k][n] = h;
    g_B[1][k][n] = l;
    g_acc[k][n] = 0.0f;
    if (k == 0 && n == 0) g_any = 0;
}

// ---------------------------------------------------------------------------
// mma_kernel: grid (32 M-tiles, 16 K-splits), 256 threads, 8 warps x 16 rows.
// A fragments built in registers from nei (int32 -> bf16 {0,1}); B via
// ldmatrix.x2.trans from SMEM; mma.sync m16n8k16 bf16, fp32 accum.
// Split-K reduced via red.global.add into g_acc.
// ---------------------------------------------------------------------------
__global__ void __launch_bounds__(THREADS, 2)
mma_kernel(const int* __restrict__ nei) {
    extern __shared__ char smem[];
    const uint32_t sb = smem_u32(smem);

    const int tid  = threadIdx.x;
    const int wid  = tid >> 5;
    const int lane = tid & 31;
    const int g    = lane >> 2;      // fragment row group 0..7
    const int tq   = lane & 3;       // fragment k/col group 0..3

    const int i0 = blockIdx.x * MTILE;
    const int ks = blockIdx.y;
    const int k0 = ks * KC;

    // --- stage B hi/lo slice [KC][72] into SMEM (rows contiguous in global) ---
    {
        const uint4* s0 = (const uint4*)&g_B[0][k0][0];
        const uint4* s1 = (const uint4*)&g_B[1][k0][0];
        uint4* d0 = (uint4*)smem;
        uint4* d1 = (uint4*)(smem + SM_PLANE);
#pragma unroll
        for (int it = 0; it < SM_PLANE / 16 / THREADS; it++) {
            int idx = tid + it * THREADS;
            d0[idx] = s0[idx];
            d1[idx] = s1[idx];
        }
    }
    __syncthreads();

    const int row = i0 + wid * 16 + g;          // this lane's fragment rows: row, row+8

    float d[9][4];
#pragma unroll
    for (int nf = 0; nf < 9; nf++)
#pragma unroll
        for (int c = 0; c < 4; c++) d[nf][c] = 0.0f;

    const int* pa0 = nei + (size_t)row * P + k0 + tq * 2;

    // prologue: A loads for t=0
    int2 v00 = *(const int2*)(pa0);
    int2 v01 = *(const int2*)(pa0 + 8);
    int2 v10 = *(const int2*)(pa0 + (size_t)8 * P);
    int2 v11 = *(const int2*)(pa0 + (size_t)8 * P + 8);

#pragma unroll 1
    for (int t = 0; t < KC / 16; t++) {
        uint32_t a[4];
        a[0] = pack01(v00.x, v00.y);
        a[1] = pack01(v10.x, v10.y);
        a[2] = pack01(v01.x, v01.y);
        a[3] = pack01(v11.x, v11.y);

        // prefetch A for t+1 (overlaps with B ldsm + mma below)
        if (t + 1 < KC / 16) {
            const int* pa = pa0 + (t + 1) * 16;
            v00 = *(const int2*)(pa);
            v01 = *(const int2*)(pa + 8);
            v10 = *(const int2*)(pa + (size_t)8 * P);
            v11 = *(const int2*)(pa + (size_t)8 * P + 8);
        }

        // B fragments: only one (2-reg) fragment live at a time
        const uint32_t lrow = sb + (t * 16 + (lane & 15)) * BROW;
#pragma unroll
        for (int nf = 0; nf < 9; nf++) {
            uint32_t b0, b1;
            ldsm_x2_t(b0, b1, lrow + nf * 16);
            mma16816(d[nf], a, b0, b1);
        }
#pragma unroll
        for (int nf = 0; nf < 8; nf++) {
            uint32_t b0, b1;
            ldsm_x2_t(b0, b1, lrow + SM_PLANE + nf * 16);
            mma16816(d[nf], a, b0, b1);
        }
    }

    // --- any-neighbor flag: count column = col 64 = (nf=8, tq=0, comps 0/2) ---
    {
        bool has = (tq == 0) && (d[8][0] > 0.5f || d[8][2] > 0.5f);
        unsigned b = __ballot_sync(0xffffffffu, has);
        if (lane == 0 && b) atomicOr(&g_any, 1);
    }

    // --- split-K reduce into g_acc[row][col] via red.global.add ---
    float* gp0 = &g_acc[row][tq * 2];
    float* gp1 = &g_acc[row + 8][tq * 2];
#pragma unroll
    for (int nf = 0; nf < 9; nf++) {
        atomicAdd(gp0 + nf * 8,     d[nf][0]);
        atomicAdd(gp0 + nf * 8 + 1, d[nf][1]);
        atomicAdd(gp1 + nf * 8,     d[nf][2]);
        atomicAdd(gp1 + nf * 8 + 1, d[nf][3]);
    }
}

// ---------------------------------------------------------------------------
__global__ void finalize_kernel(const float* __restrict__ hidden,
                                float* __restrict__ out) {
    int gidx = blockIdx.x * blockDim.x + threadIdx.x;   // 0 .. P*64-1
    int i = gidx >> 6, c = gidx & 63;
    float s  = g_acc[i][c];
    float kf = g_acc[i][MDIM];
    float denom = kf + (4096.0f - kf) * expf(-1.000001f);
    float cs = 1.0f / denom;
    out[gidx] = (g_any > 0) ? (cs * s) : hidden[gidx];
}

// ---------------------------------------------------------------------------
extern "C" void kernel_launch(void* const* d_in, const int* in_sizes, int n_in,
                              void* d_out, int out_size) {
    const float* hidden = nullptr;
    const int* nei = nullptr;
    for (int i = 0; i < n_in; i++) {
        if (in_sizes[i] == P * MDIM)   hidden = (const float*)d_in[i];
        else if (in_sizes[i] == P * P) nei    = (const int*)d_in[i];
    }
    float* out = (float*)d_out;

    cudaFuncSetAttribute(mma_kernel, cudaFuncAttributeMaxDynamicSharedMemorySize, SM_TOTAL);

    prep_kernel<<<4096 / 8, dim3(NB, 8)>>>(hidden);
    mma_kernel<<<dim3(P / MTILE, NJ), THREADS, SM_TOTAL>>>(nei);
    finalize_kernel<<<(P * MDIM) / 256, 256>>>(hidden, out);
    (void)out_size;
}